// round 8
// baseline (speedup 1.0000x reference)
#include <cuda_runtime.h>

// ---------------- problem constants ----------------
#define NSEQ  704          // B*F = 8*88
#define TT    512
#define CDIM  64
#define HDIM  64
#define GDIM  192          // 3*H
#define MROWS (NSEQ*TT)    // 360448
#define SPC   10           // sequences per fused CTA
#define NCTA  71           // ceil(704/10); grid (71,2) = 142 CTAs ~ 1 wave @ occ 1

// ---------------- scratch (device globals; no allocation) ----------------
__device__ float g_h1[(size_t)MROWS * 128];   // layer-0 output / layer-1 input
__device__ float g_h2[(size_t)MROWS * 128];   // layer-1 output / fc input

typedef unsigned long long u64;

__device__ __forceinline__ u64 fma2(u64 a, u64 b, u64 c) {
    u64 d;
    asm("fma.rn.f32x2 %0, %1, %2, %3;" : "=l"(d) : "l"(a), "l"(b), "l"(c));
    return d;
}
__device__ __forceinline__ float2 u2f(u64 v) {
    float2 r;
    asm("mov.b64 {%0,%1}, %2;" : "=f"(r.x), "=f"(r.y) : "l"(v));
    return r;
}
__device__ __forceinline__ float tanh_fast(float x) {
    float y;
    asm("tanh.approx.f32 %0, %1;" : "=f"(y) : "f"(x));
    return y;
}
__device__ __forceinline__ float sig_fast(float x) {
    return 0.5f * tanh_fast(0.5f * x) + 0.5f;
}
__device__ __forceinline__ float sig_acc(float x) {
    return __fdividef(1.f, 1.f + __expf(-x));
}

// ---------------- fused layer kernel ----------------
// 384 threads. Threads 0-191: recurrence (Whh row in 32 u64 regs).
// Threads 192-383: input projection (Wih row in KD/2 u64 regs), producing
// pre(t+1) into a smem double buffer while the recurrence consumes pre(t).
// x rows are double-buffered in smem, prefetched 2 steps ahead (LDG->STS).
// Same 2 barriers/step order everything.
template<int KD>
__global__ __launch_bounds__(384)
void fused_kernel(const float* __restrict__ xin,
                  const float* __restrict__ Wih,   // [2][192][KD]
                  const float* __restrict__ bih,   // [2][192]
                  const float* __restrict__ Whh,   // [2][192][64]
                  const float* __restrict__ bhh)   // [2][192]
{
    const float* in = (KD == CDIM) ? xin : (const float*)g_h1;
    float*      hout = (KD == CDIM) ? (float*)g_h1 : (float*)g_h2;

    const int d   = blockIdx.y;
    const int n0  = blockIdx.x * SPC;
    const int tid = threadIdx.x;

    __shared__ float h_sh[SPC][64];
    __shared__ float s_v[SPC][256];
    __shared__ __align__(16) float xs[2][SPC * KD];
    __shared__ float pre_sh[2][SPC][GDIM];

    const int t0 = d ? (TT - 1) : 0;
    const int dt = d ? -1 : 1;

    // per-role weight registers
    u64 wreg[KD / 2];
    float bias_r;
    if (tid < GDIM) {
        const u64* wr = (const u64*)(Whh + ((size_t)d * GDIM + tid) * HDIM);
#pragma unroll
        for (int q = 0; q < 32; q++) wreg[q] = wr[q];
        bias_r = bhh[d * GDIM + tid];
    } else {
        const int pid = tid - GDIM;
        const u64* wr = (const u64*)(Wih + ((size_t)d * GDIM + pid) * KD);
#pragma unroll
        for (int q = 0; q < KD / 2; q++) wreg[q] = wr[q];
        bias_r = bih[d * GDIM + pid];
    }

    for (int i = tid; i < SPC * 64; i += 384) ((float*)h_sh)[i] = 0.f;

    // prologue: x(t0) -> xs[0], x(t0+dt) -> xs[1]
    const int F4 = SPC * KD / 4;
    for (int i = tid; i < F4; i += 384) {
        int row = i / (KD / 4), j = i % (KD / 4);
        int n = n0 + row; if (n >= NSEQ) n = NSEQ - 1;
        const float4* base = (const float4*)(in + ((size_t)n * TT) * KD);
        ((float4*)xs[0])[i] = base[(size_t)t0 * (KD / 4) + j];
        ((float4*)xs[1])[i] = base[(size_t)(t0 + dt) * (KD / 4) + j];
    }
    __syncthreads();

    // prologue: pre(t0) -> pre_sh[0]
    if (tid >= GDIM) {
        const int pid = tid - GDIM;
#pragma unroll 1
        for (int seq = 0; seq < SPC; seq++) {
            const ulonglong2* x2 = (const ulonglong2*)(xs[0] + seq * KD);
            u64 a0 = 0, a1 = 0, a2 = 0, a3 = 0;
#pragma unroll
            for (int q = 0; q < KD / 4; q += 2) {
                ulonglong2 va = x2[q], vb = x2[q + 1];
                a0 = fma2(wreg[2 * q + 0], va.x, a0);
                a1 = fma2(wreg[2 * q + 1], va.y, a1);
                a2 = fma2(wreg[2 * q + 2], vb.x, a2);
                a3 = fma2(wreg[2 * q + 3], vb.y, a3);
            }
            float2 f0 = u2f(a0), f1 = u2f(a1), f2_ = u2f(a2), f3 = u2f(a3);
            pre_sh[0][seq][pid] = ((f0.x + f0.y) + (f1.x + f1.y)) +
                                  ((f2_.x + f2_.y) + (f3.x + f3.y)) + bias_r;
        }
    }
    __syncthreads();

    int t = t0;
#pragma unroll 1
    for (int s = 0; s < TT; s++) {
        const int cur = s & 1, nxt = cur ^ 1;

        // ---- phase A ----
        if (tid < GDIM) {
            // recurrence dot products: consume pre_sh[cur], h_sh
#pragma unroll 1
            for (int seq = 0; seq < SPC; seq++) {
                const ulonglong2* h2 = (const ulonglong2*)h_sh[seq];
                u64 a0 = 0, a1 = 0, a2 = 0, a3 = 0;
#pragma unroll
                for (int q = 0; q < 16; q += 2) {
                    ulonglong2 hv = h2[q], hw = h2[q + 1];
                    a0 = fma2(wreg[2 * q + 0], hv.x, a0);
                    a1 = fma2(wreg[2 * q + 1], hv.y, a1);
                    a2 = fma2(wreg[2 * q + 2], hw.x, a2);
                    a3 = fma2(wreg[2 * q + 3], hw.y, a3);
                }
                float2 f0 = u2f(a0), f1 = u2f(a1), f2_ = u2f(a2), f3 = u2f(a3);
                float hh = ((f0.x + f0.y) + (f1.x + f1.y)) +
                           ((f2_.x + f2_.y) + (f3.x + f3.y)) + bias_r;
                float pcv = pre_sh[cur][seq][tid];
                if (tid < 128) {
                    s_v[seq][tid] = hh + pcv;      // r, z pre-activations
                } else {
                    s_v[seq][tid]      = hh;       // hn
                    s_v[seq][tid + 64] = pcv;      // pn
                }
            }
        } else {
            const int pid = tid - GDIM;
            constexpr int NLD = (SPC * KD / 4 + 191) / 192;
            float4 ldv[NLD];
            // prefetch x(t+2dt)
            if (s < TT - 2) {
                const int t2 = t + 2 * dt;
#pragma unroll
                for (int u = 0; u < NLD; u++) {
                    int i = pid + u * 192;
                    if (i < F4) {
                        int row = i / (KD / 4), j = i % (KD / 4);
                        int n = n0 + row; if (n >= NSEQ) n = NSEQ - 1;
                        ldv[u] = __ldg((const float4*)(in + ((size_t)n * TT + t2) * KD) + j);
                    }
                }
            }
            // compute pre(t+dt) from xs[nxt]
            if (s < TT - 1) {
#pragma unroll 1
                for (int seq = 0; seq < SPC; seq++) {
                    const ulonglong2* x2 = (const ulonglong2*)(xs[nxt] + seq * KD);
                    u64 a0 = 0, a1 = 0, a2 = 0, a3 = 0;
#pragma unroll
                    for (int q = 0; q < KD / 4; q += 2) {
                        ulonglong2 va = x2[q], vb = x2[q + 1];
                        a0 = fma2(wreg[2 * q + 0], va.x, a0);
                        a1 = fma2(wreg[2 * q + 1], va.y, a1);
                        a2 = fma2(wreg[2 * q + 2], vb.x, a2);
                        a3 = fma2(wreg[2 * q + 3], vb.y, a3);
                    }
                    float2 f0 = u2f(a0), f1 = u2f(a1), f2_ = u2f(a2), f3 = u2f(a3);
                    pre_sh[nxt][seq][pid] = ((f0.x + f0.y) + (f1.x + f1.y)) +
                                            ((f2_.x + f2_.y) + (f3.x + f3.y)) + bias_r;
                }
            }
            // stage prefetched x into xs[cur] (read next step, after 2 barriers)
            if (s < TT - 2) {
#pragma unroll
                for (int u = 0; u < NLD; u++) {
                    int i = pid + u * 192;
                    if (i < F4) ((float4*)xs[cur])[i] = ldv[u];
                }
            }
        }
        __syncthreads();

        // ---- phase B: activations (all 384 threads; 640 slots) ----
        {
            auto act = [&](int slot) {
                int seq = slot >> 6, idx = slot & 63;
                float r    = sig_fast(s_v[seq][idx]);
                float z    = sig_fast(s_v[seq][64 + idx]);
                float nn   = tanh_fast(s_v[seq][192 + idx] + r * s_v[seq][128 + idx]);
                float hold = h_sh[seq][idx];
                float hnew = nn + z * (hold - nn);
                h_sh[seq][idx] = hnew;
                int n = n0 + seq;
                if (n < NSEQ)
                    hout[((size_t)n * TT + t) * 128 + d * 64 + idx] = hnew;
            };
            act(tid);
            if (tid < SPC * 64 - 384) act(tid + 384);   // 256 extra slots
        }
        __syncthreads();

        t += dt;
    }
}

// ---------------- FC head: out = sigmoid(h2 . fc_w + fc_b) ----------------
__global__ void fc_kernel(const float* __restrict__ fcw,
                          const float* __restrict__ fcb,
                          float* __restrict__ out)
{
    int g    = blockIdx.x * 8 + (threadIdx.x >> 5);
    int lane = threadIdx.x & 31;
    if (g >= MROWS) return;
    float4 v = *(const float4*)(g_h2 + (size_t)g * 128 + lane * 4);
    float4 w = *(const float4*)(fcw + lane * 4);
    float dot = v.x * w.x + v.y * w.y + v.z * w.z + v.w * w.w;
#pragma unroll
    for (int o = 16; o > 0; o >>= 1) dot += __shfl_down_sync(0xffffffffu, dot, o);
    if (lane == 0) {
        int nidx = g / TT, t = g % TT;
        int b = nidx / 88, f = nidx % 88;
        out[((size_t)b * TT + t) * 88 + f] = sig_acc(dot + fcb[0]);
    }
}

// ---------------- launch ----------------
extern "C" void kernel_launch(void* const* d_in, const int* in_sizes, int n_in,
                              void* d_out, int out_size)
{
    const float* x    = (const float*)d_in[0];
    const float* Wih0 = (const float*)d_in[1];
    const float* Whh0 = (const float*)d_in[2];
    const float* bih0 = (const float*)d_in[3];
    const float* bhh0 = (const float*)d_in[4];
    const float* Wih1 = (const float*)d_in[5];
    const float* Whh1 = (const float*)d_in[6];
    const float* bih1 = (const float*)d_in[7];
    const float* bhh1 = (const float*)d_in[8];
    const float* fcw  = (const float*)d_in[9];
    const float* fcb  = (const float*)d_in[10];
    float* out = (float*)d_out;

    dim3 fg(NCTA, 2);

    fused_kernel<CDIM><<<fg, 384>>>(x, Wih0, bih0, Whh0, bhh0);       // layer 0
    fused_kernel<2 * HDIM><<<fg, 384>>>(x, Wih1, bih1, Whh1, bhh1);   // layer 1
    fc_kernel<<<MROWS / 8, 256>>>(fcw, fcb, out);                     // FC + sigmoid
}